// round 4
// baseline (speedup 1.0000x reference)
#include <cuda_runtime.h>

#define BATCH 16
#define HDIM 512
#define WDIM 512
#define HW (HDIM * WDIM)
#define NTOT (BATCH * 3 * HW)
#define STRIPS 128                 // per batch, 4 rows each
#define GRID (BATCH * STRIPS)      // 2048 blocks

__device__ double       g_acc;
__device__ unsigned int g_count;

__global__ void __launch_bounds__(256, 4)
fused_loss_kernel(const float* __restrict__ pred,
                  const float* __restrict__ targ,
                  const int*   __restrict__ lm,
                  float*       __restrict__ out) {
    __shared__ float scx[32], scy[32];
    __shared__ int   s_iseye[32];
    __shared__ int   s_cnt;
    __shared__ float s_warp[8];

    const int bid   = blockIdx.x;
    const int b     = bid >> 7;
    const int strip = bid & 127;
    const int y0    = strip << 2;          // 4-row strip
    const int t     = threadIdx.x;

    // ---- Issue landmark load immediately (latency hidden by main loads) ----
    int lmx = 0, lmy = 0;
    if (t < 32) {
        lmx = lm[(b * 68 + 36 + t) * 2 + 0];
        lmy = lm[(b * 68 + 36 + t) * 2 + 1];
    }
    if (t == 0) s_cnt = 0;

    // Thread -> (row, 2 quads at xb and xb+256)
    const int   row  = t >> 6;             // 0..3
    const int   lane = t & 63;
    const int   y    = y0 + row;
    const float yf   = (float)y;
    const int   xb   = lane << 2;
    const int   base = b * 3 * HW + y * WDIM + xb;

    // ---- Front-batch 8 float4 pairs (quads 0/1 x channels 0/1) NOW ----
    const float4 pa = *reinterpret_cast<const float4*>(pred + base);
    const float4 qa = *reinterpret_cast<const float4*>(targ + base);
    const float4 pb = *reinterpret_cast<const float4*>(pred + base + 256);
    const float4 qb = *reinterpret_cast<const float4*>(targ + base + 256);
    const float4 pc = *reinterpret_cast<const float4*>(pred + base + HW);
    const float4 qc = *reinterpret_cast<const float4*>(targ + base + HW);
    const float4 pd = *reinterpret_cast<const float4*>(pred + base + HW + 256);
    const float4 qd = *reinterpret_cast<const float4*>(targ + base + HW + 256);

    // ---- Landmark filter (runs under load latency) ----
    __syncthreads();
    if (t < 32) {
        int cx = min(max(lmx, 0), WDIM - 1);
        int cy = min(max(lmy, 0), HDIM - 1);
        if (cy >= y0 - 15 && cy <= y0 + 18) {          // loose superset
            int slot = atomicAdd(&s_cnt, 1);
            scx[slot]     = (float)cx;
            scy[slot]     = (float)cy;
            s_iseye[slot] = (t < 12);
        }
    }
    __syncthreads();
    const int cnt = s_cnt;

    // ---- Weight computation (independent of main loads) ----
    float w[2][4];
    #pragma unroll
    for (int k = 0; k < 2; k++) {
        const float xf = (float)(xb + (k << 8));
        float e0 = 0.f, e1 = 0.f, e2 = 0.f, e3 = 0.f;
        float m0 = 0.f, m1 = 0.f, m2 = 0.f, m3 = 0.f;
        for (int j = 0; j < cnt; j++) {
            const float cx = scx[j], cy = scy[j];
            const float dy  = yf - cy;
            const float dy2 = dy * dy;
            if (dy2 < 225.f && fabsf(xf + 1.5f - cx) < 18.f) {
                const float dx0 = xf - cx;
                const float dx1 = dx0 + 1.f, dx2 = dx0 + 2.f, dx3 = dx0 + 3.f;
                const float v0 = 1.f - sqrtf(fmaf(dx0, dx0, dy2)) * (1.f / 15.f);
                const float v1 = 1.f - sqrtf(fmaf(dx1, dx1, dy2)) * (1.f / 15.f);
                const float v2 = 1.f - sqrtf(fmaf(dx2, dx2, dy2)) * (1.f / 15.f);
                const float v3 = 1.f - sqrtf(fmaf(dx3, dx3, dy2)) * (1.f / 15.f);
                if (s_iseye[j]) {
                    e0 = fmaxf(e0, v0); e1 = fmaxf(e1, v1);
                    e2 = fmaxf(e2, v2); e3 = fmaxf(e3, v3);
                } else {
                    m0 = fmaxf(m0, v0); m1 = fmaxf(m1, v1);
                    m2 = fmaxf(m2, v2); m3 = fmaxf(m3, v3);
                }
            }
        }
        w[k][0] = fmaf(fminf(e0 + m0, 1.f), 299.f, 1.f);
        w[k][1] = fmaf(fminf(e1 + m1, 1.f), 299.f, 1.f);
        w[k][2] = fmaf(fminf(e2 + m2, 1.f), 299.f, 1.f);
        w[k][3] = fmaf(fminf(e3 + m3, 1.f), 299.f, 1.f);
    }

    // ---- Late loads: channel 2 (issue before consuming the front regs) ----
    const float4 pe = *reinterpret_cast<const float4*>(pred + base + 2 * HW);
    const float4 qe = *reinterpret_cast<const float4*>(targ + base + 2 * HW);
    const float4 pf = *reinterpret_cast<const float4*>(pred + base + 2 * HW + 256);
    const float4 qf = *reinterpret_cast<const float4*>(targ + base + 2 * HW + 256);

    // ---- Consume ----
    float acc = 0.0f;
    acc += w[0][0] * fabsf(pa.x - qa.x);
    acc += w[0][1] * fabsf(pa.y - qa.y);
    acc += w[0][2] * fabsf(pa.z - qa.z);
    acc += w[0][3] * fabsf(pa.w - qa.w);
    acc += w[1][0] * fabsf(pb.x - qb.x);
    acc += w[1][1] * fabsf(pb.y - qb.y);
    acc += w[1][2] * fabsf(pb.z - qb.z);
    acc += w[1][3] * fabsf(pb.w - qb.w);
    acc += w[0][0] * fabsf(pc.x - qc.x);
    acc += w[0][1] * fabsf(pc.y - qc.y);
    acc += w[0][2] * fabsf(pc.z - qc.z);
    acc += w[0][3] * fabsf(pc.w - qc.w);
    acc += w[1][0] * fabsf(pd.x - qd.x);
    acc += w[1][1] * fabsf(pd.y - qd.y);
    acc += w[1][2] * fabsf(pd.z - qd.z);
    acc += w[1][3] * fabsf(pd.w - qd.w);
    acc += w[0][0] * fabsf(pe.x - qe.x);
    acc += w[0][1] * fabsf(pe.y - qe.y);
    acc += w[0][2] * fabsf(pe.z - qe.z);
    acc += w[0][3] * fabsf(pe.w - qe.w);
    acc += w[1][0] * fabsf(pf.x - qf.x);
    acc += w[1][1] * fabsf(pf.y - qf.y);
    acc += w[1][2] * fabsf(pf.z - qf.z);
    acc += w[1][3] * fabsf(pf.w - qf.w);

    // ---- Block reduction + device-side finalize ----
    #pragma unroll
    for (int off = 16; off; off >>= 1)
        acc += __shfl_down_sync(0xffffffffu, acc, off);

    const int lane32 = t & 31, wid = t >> 5;
    if (lane32 == 0) s_warp[wid] = acc;
    __syncthreads();
    if (wid == 0) {
        acc = (lane32 < 8) ? s_warp[lane32] : 0.0f;
        #pragma unroll
        for (int off = 4; off; off >>= 1)
            acc += __shfl_down_sync(0xffffffffu, acc, off);

        if (lane32 == 0) {
            atomicAdd(&g_acc, (double)acc);
            __threadfence();
            unsigned int ticket = atomicAdd(&g_count, 1u);
            if (ticket == GRID - 1) {
                __threadfence();
                double total = *((volatile double*)&g_acc);
                out[0] = (float)(total * (1.0 / (double)NTOT));
                g_acc   = 0.0;          // clean state for next graph replay
                g_count = 0u;
            }
        }
    }
}

extern "C" void kernel_launch(void* const* d_in, const int* in_sizes, int n_in,
                              void* d_out, int out_size) {
    const float* pred = (const float*)d_in[0];
    const float* targ = (const float*)d_in[1];
    const int*   lm   = (const int*)d_in[2];
    float*       out  = (float*)d_out;

    fused_loss_kernel<<<GRID, 256>>>(pred, targ, lm, out);
}

// round 5
// speedup vs baseline: 1.1468x; 1.1468x over previous
#include <cuda_runtime.h>

#define BATCH 16
#define HDIM 512
#define WDIM 512
#define HW (HDIM * WDIM)
#define NTOT (BATCH * 3 * HW)
#define STRIPS 256                 // per batch, 2 rows each
#define GRID (BATCH * STRIPS)      // 4096 blocks

__device__ double       g_acc;
__device__ unsigned int g_count;

__global__ void __launch_bounds__(128, 12)
fused_loss_kernel(const float* __restrict__ pred,
                  const float* __restrict__ targ,
                  const int*   __restrict__ lm,
                  float*       __restrict__ out) {
    __shared__ float scx[32], scy[32];
    __shared__ int   s_iseye[32];
    __shared__ int   s_cnt;
    __shared__ float s_warp[4];

    const int bid   = blockIdx.x;
    const int b     = bid >> 8;
    const int strip = bid & 255;
    const int y0    = strip << 1;          // 2-row strip
    const int t     = threadIdx.x;

    if (t == 0) s_cnt = 0;
    __syncthreads();

    // Filter this batch's 32 landmarks (indices 36..67) by strip y-range.
    if (t < 32) {
        int cx = lm[(b * 68 + 36 + t) * 2 + 0];
        int cy = lm[(b * 68 + 36 + t) * 2 + 1];
        cx = min(max(cx, 0), WDIM - 1);
        cy = min(max(cy, 0), HDIM - 1);
        if (cy >= y0 - 15 && cy <= y0 + 16) {          // loose superset
            int slot = atomicAdd(&s_cnt, 1);
            scx[slot]     = (float)cx;
            scy[slot]     = (float)cy;
            s_iseye[slot] = (t < 12);
        }
    }
    __syncthreads();
    const int cnt = s_cnt;

    // Thread -> (row, 2 quads at xb and xb+256). 64 threads per row.
    const int   row  = t >> 6;             // 0..1
    const int   lane = t & 63;
    const int   y    = y0 + row;
    const float yf   = (float)y;
    const int   xb   = lane << 2;
    const int   base = b * 3 * HW + y * WDIM + xb;

    // ---- Phase 1: weights (skipped entirely when no landmark hits strip) ----
    float w[2][4] = {{1.f, 1.f, 1.f, 1.f}, {1.f, 1.f, 1.f, 1.f}};
    if (cnt > 0) {
        #pragma unroll
        for (int k = 0; k < 2; k++) {
            const float xf = (float)(xb + (k << 8));
            float e0 = 0.f, e1 = 0.f, e2 = 0.f, e3 = 0.f;
            float m0 = 0.f, m1 = 0.f, m2 = 0.f, m3 = 0.f;
            for (int j = 0; j < cnt; j++) {
                const float cx = scx[j], cy = scy[j];
                const float dy  = yf - cy;
                const float dy2 = dy * dy;
                if (dy2 < 225.f && fabsf(xf + 1.5f - cx) < 18.f) {
                    const float dx0 = xf - cx;
                    const float dx1 = dx0 + 1.f, dx2 = dx0 + 2.f, dx3 = dx0 + 3.f;
                    const float v0 = 1.f - sqrtf(fmaf(dx0, dx0, dy2)) * (1.f / 15.f);
                    const float v1 = 1.f - sqrtf(fmaf(dx1, dx1, dy2)) * (1.f / 15.f);
                    const float v2 = 1.f - sqrtf(fmaf(dx2, dx2, dy2)) * (1.f / 15.f);
                    const float v3 = 1.f - sqrtf(fmaf(dx3, dx3, dy2)) * (1.f / 15.f);
                    if (s_iseye[j]) {
                        e0 = fmaxf(e0, v0); e1 = fmaxf(e1, v1);
                        e2 = fmaxf(e2, v2); e3 = fmaxf(e3, v3);
                    } else {
                        m0 = fmaxf(m0, v0); m1 = fmaxf(m1, v1);
                        m2 = fmaxf(m2, v2); m3 = fmaxf(m3, v3);
                    }
                }
            }
            w[k][0] = fmaf(fminf(e0 + m0, 1.f), 299.f, 1.f);
            w[k][1] = fmaf(fminf(e1 + m1, 1.f), 299.f, 1.f);
            w[k][2] = fmaf(fminf(e2 + m2, 1.f), 299.f, 1.f);
            w[k][3] = fmaf(fminf(e3 + m3, 1.f), 299.f, 1.f);
        }
    }

    // ---- Phase 2: 6 independent float4 load-pairs, straight-line ----
    float acc = 0.0f;
    #pragma unroll
    for (int k = 0; k < 2; k++) {
        #pragma unroll
        for (int c = 0; c < 3; c++) {
            const int    off = c * HW + (k << 8);
            const float4 p   = *reinterpret_cast<const float4*>(pred + base + off);
            const float4 tt  = *reinterpret_cast<const float4*>(targ + base + off);
            acc += w[k][0] * fabsf(p.x - tt.x);
            acc += w[k][1] * fabsf(p.y - tt.y);
            acc += w[k][2] * fabsf(p.z - tt.z);
            acc += w[k][3] * fabsf(p.w - tt.w);
        }
    }

    // ---- Block reduction (4 warps) + device-side finalize ----
    #pragma unroll
    for (int off = 16; off; off >>= 1)
        acc += __shfl_down_sync(0xffffffffu, acc, off);

    const int lane32 = t & 31, wid = t >> 5;
    if (lane32 == 0) s_warp[wid] = acc;
    __syncthreads();
    if (wid == 0) {
        acc = (lane32 < 4) ? s_warp[lane32] : 0.0f;
        acc += __shfl_down_sync(0xffffffffu, acc, 2);
        acc += __shfl_down_sync(0xffffffffu, acc, 1);

        if (lane32 == 0) {
            atomicAdd(&g_acc, (double)acc);
            __threadfence();
            unsigned int ticket = atomicAdd(&g_count, 1u);
            if (ticket == GRID - 1) {
                __threadfence();
                double total = *((volatile double*)&g_acc);
                out[0] = (float)(total * (1.0 / (double)NTOT));
                g_acc   = 0.0;          // clean state for next graph replay
                g_count = 0u;
            }
        }
    }
}

extern "C" void kernel_launch(void* const* d_in, const int* in_sizes, int n_in,
                              void* d_out, int out_size) {
    const float* pred = (const float*)d_in[0];
    const float* targ = (const float*)d_in[1];
    const int*   lm   = (const int*)d_in[2];
    float*       out  = (float*)d_out;

    fused_loss_kernel<<<GRID, 128>>>(pred, targ, lm, out);
}

// round 6
// speedup vs baseline: 1.2576x; 1.0966x over previous
#include <cuda_runtime.h>

#define BATCH 16
#define HDIM 512
#define WDIM 512
#define HW (HDIM * WDIM)
#define NTOT (BATCH * 3 * HW)
#define STRIPS_TOT (BATCH * 256)   // 2-row strips, 256 per batch = 4096
#define GRID 592                   // 148 SMs x 4 blocks -> single wave
#define THREADS 256

__device__ double       g_acc;
__device__ unsigned int g_count;

__global__ void __launch_bounds__(THREADS, 4)
fused_loss_kernel(const float* __restrict__ pred,
                  const float* __restrict__ targ,
                  const int*   __restrict__ lm,
                  float*       __restrict__ out) {
    __shared__ float    scx[BATCH * 32];
    __shared__ float    scy[BATCH * 32];
    __shared__ unsigned s_mask[2];
    __shared__ float    s_warp[8];

    const int t   = threadIdx.x;
    const int bid = blockIdx.x;

    // ---- Load ALL landmarks (16 batches x 32) into smem once ----
    for (int i = t; i < BATCH * 32; i += THREADS) {
        const int b = i >> 5, j = i & 31;
        int cx = lm[(b * 68 + 36 + j) * 2 + 0];
        int cy = lm[(b * 68 + 36 + j) * 2 + 1];
        scx[i] = (float)min(max(cx, 0), WDIM - 1);
        scy[i] = (float)min(max(cy, 0), HDIM - 1);
    }

    const int nIter = (STRIPS_TOT - bid + GRID - 1) / GRID;   // 6 or 7

    __syncthreads();

    // ---- Prologue: mask for iteration 0 (warp 0 ballot) ----
    if (t < 32) {
        const int sid = bid;
        const int b   = sid >> 8;
        const float y0 = (float)((sid & 255) << 1);
        const float cy = scy[b * 32 + t];
        const bool hit = (cy >= y0 - 15.f) && (cy <= y0 + 16.f);
        const unsigned m = __ballot_sync(0xffffffffu, hit);
        if (t == 0) s_mask[0] = m;
    }
    __syncthreads();

    // Thread -> (row 0/1 of strip, one quad). 128 threads per 512-px row.
    const int   row = t >> 7;
    const int   xq  = (t & 127) << 2;
    const float xf  = (float)xq;

    float acc = 0.0f;

    for (int it = 0; it < nIter; ++it) {
        const int sid = bid + it * GRID;
        const int b   = sid >> 8;
        const int y0  = (sid & 255) << 1;
        const int y   = y0 + row;
        const float yf = (float)y;

        // ---- Issue all 6 float4 pairs for this iteration NOW ----
        const float4* pp = reinterpret_cast<const float4*>(pred + b * 3 * HW + y * WDIM + xq);
        const float4* qq = reinterpret_cast<const float4*>(targ + b * 3 * HW + y * WDIM + xq);
        const float4 p0 = pp[0];          const float4 q0 = qq[0];
        const float4 p1 = pp[HW / 4];     const float4 q1 = qq[HW / 4];
        const float4 p2 = pp[HW / 2];     const float4 q2 = qq[HW / 2];

        // ---- Warp 0: build next iteration's landmark mask ----
        if (t < 32 && it + 1 < nIter) {
            const int sid2 = sid + GRID;
            const int b2   = sid2 >> 8;
            const float y02 = (float)((sid2 & 255) << 1);
            const float cy2 = scy[b2 * 32 + t];
            const bool hit = (cy2 >= y02 - 15.f) && (cy2 <= y02 + 16.f);
            const unsigned m2 = __ballot_sync(0xffffffffu, hit);
            if (t == 0) s_mask[(it + 1) & 1] = m2;
        }

        // ---- Weights: walk set bits of this strip's mask (~2 avg) ----
        float w0 = 1.f, w1 = 1.f, w2 = 1.f, w3 = 1.f;
        unsigned m = s_mask[it & 1];
        if (m) {
            float e0 = 0.f, e1 = 0.f, e2 = 0.f, e3 = 0.f;
            float f0 = 0.f, f1 = 0.f, f2 = 0.f, f3 = 0.f;
            do {
                const int j = __ffs(m) - 1;
                m &= m - 1;
                const float cx = scx[b * 32 + j];
                const float cy = scy[b * 32 + j];
                const float dy  = yf - cy;
                const float dy2 = dy * dy;
                if (dy2 < 225.f && fabsf(xf + 1.5f - cx) < 18.f) {
                    const float dx0 = xf - cx;
                    const float dx1 = dx0 + 1.f, dx2 = dx0 + 2.f, dx3 = dx0 + 3.f;
                    const float v0 = 1.f - sqrtf(fmaf(dx0, dx0, dy2)) * (1.f / 15.f);
                    const float v1 = 1.f - sqrtf(fmaf(dx1, dx1, dy2)) * (1.f / 15.f);
                    const float v2 = 1.f - sqrtf(fmaf(dx2, dx2, dy2)) * (1.f / 15.f);
                    const float v3 = 1.f - sqrtf(fmaf(dx3, dx3, dy2)) * (1.f / 15.f);
                    if (j < 12) {
                        e0 = fmaxf(e0, v0); e1 = fmaxf(e1, v1);
                        e2 = fmaxf(e2, v2); e3 = fmaxf(e3, v3);
                    } else {
                        f0 = fmaxf(f0, v0); f1 = fmaxf(f1, v1);
                        f2 = fmaxf(f2, v2); f3 = fmaxf(f3, v3);
                    }
                }
            } while (m);
            w0 = fmaf(fminf(e0 + f0, 1.f), 299.f, 1.f);
            w1 = fmaf(fminf(e1 + f1, 1.f), 299.f, 1.f);
            w2 = fmaf(fminf(e2 + f2, 1.f), 299.f, 1.f);
            w3 = fmaf(fminf(e3 + f3, 1.f), 299.f, 1.f);
        }

        // Publish next mask / recycle buffers before consuming loads.
        __syncthreads();

        // ---- Consume ----
        acc += w0 * fabsf(p0.x - q0.x);
        acc += w1 * fabsf(p0.y - q0.y);
        acc += w2 * fabsf(p0.z - q0.z);
        acc += w3 * fabsf(p0.w - q0.w);
        acc += w0 * fabsf(p1.x - q1.x);
        acc += w1 * fabsf(p1.y - q1.y);
        acc += w2 * fabsf(p1.z - q1.z);
        acc += w3 * fabsf(p1.w - q1.w);
        acc += w0 * fabsf(p2.x - q2.x);
        acc += w1 * fabsf(p2.y - q2.y);
        acc += w2 * fabsf(p2.z - q2.z);
        acc += w3 * fabsf(p2.w - q2.w);
    }

    // ---- Block reduction (8 warps) + device-side finalize ----
    #pragma unroll
    for (int off = 16; off; off >>= 1)
        acc += __shfl_down_sync(0xffffffffu, acc, off);

    const int lane32 = t & 31, wid = t >> 5;
    if (lane32 == 0) s_warp[wid] = acc;
    __syncthreads();
    if (wid == 0) {
        acc = (lane32 < 8) ? s_warp[lane32] : 0.0f;
        #pragma unroll
        for (int off = 4; off; off >>= 1)
            acc += __shfl_down_sync(0xffffffffu, acc, off);

        if (lane32 == 0) {
            atomicAdd(&g_acc, (double)acc);
            __threadfence();
            unsigned int ticket = atomicAdd(&g_count, 1u);
            if (ticket == GRID - 1) {
                __threadfence();
                double total = *((volatile double*)&g_acc);
                out[0] = (float)(total * (1.0 / (double)NTOT));
                g_acc   = 0.0;          // clean state for next graph replay
                g_count = 0u;
            }
        }
    }
}

extern "C" void kernel_launch(void* const* d_in, const int* in_sizes, int n_in,
                              void* d_out, int out_size) {
    const float* pred = (const float*)d_in[0];
    const float* targ = (const float*)d_in[1];
    const int*   lm   = (const int*)d_in[2];
    float*       out  = (float*)d_out;

    fused_loss_kernel<<<GRID, THREADS>>>(pred, targ, lm, out);
}